// round 5
// baseline (speedup 1.0000x reference)
#include <cuda_runtime.h>
#include <math.h>

// ---------------------------------------------------------------------------
// Fixed problem shapes (fast path: uniform peaks)
// ---------------------------------------------------------------------------
#define BATCH      2
#define NUM_PEAKS  64
#define PEAKS      128          // BATCH * NUM_PEAKS
#define PSIZE      1000
#define MOTIF      640
#define HID        256
#define DEPTH      7
#define PROF_K     75
#define MAXLEN     1008         // padded row stride (floats)
#define GL_TOTAL   128000       // BATCH * NUM_PEAKS * PSIZE

// Ping-pong activation buffers: [2][peak][channel][MAXLEN]
__device__ float g_buf[2][PEAKS * HID * MAXLEN];
// Per-(peak, channel) mean of the final feature map
__device__ float g_mean[PEAKS * HID];

__device__ __forceinline__ float softplus_f(float x) {
    return (x > 20.f) ? x : log1pf(expf(x));
}

// Packed dual-fp32 FMA: d = a*b + c on both halves (sm_100+ f32x2 pipe, 2x rate)
__device__ __forceinline__ unsigned long long ffma2(unsigned long long a,
                                                    unsigned long long b,
                                                    unsigned long long c) {
    unsigned long long d;
    asm("fma.rn.f32x2 %0, %1, %2, %3;" : "=l"(d) : "l"(a), "l"(b), "l"(c));
    return d;
}

__device__ __forceinline__ float2 u2f2(unsigned long long u) {
    float2 f;
    asm("mov.b64 {%0, %1}, %2;" : "=f"(f.x), "=f"(f.y) : "l"(u));
    return f;
}

// ---------------------------------------------------------------------------
// Kernel 1: 1x1 motif projection  h[n][c][l] = sum_m x[gl][m] * w[c][m] + b[c]
// 128 gl x 128 c per block, 256 threads. Each thread: 8 c (stride 16) x
// 4 consecutive-gl PAIRS (f32x2 packed math).
// ---------------------------------------------------------------------------
__global__ __launch_bounds__(256)
void proj_kernel(const float* __restrict__ x,
                 const float* __restrict__ w,
                 const float* __restrict__ bias) {
    __shared__ float2 Wsd[8][128];                 // [m][c] duplicated (w,w)
    __shared__ __align__(16) float Xs[8][128];     // [m][gl]

    const int tid = threadIdx.x;
    const int tx  = tid & 15;       // gl-pair lane
    const int ty  = tid >> 4;       // c lane
    const int gl0 = blockIdx.x * 128;
    const int c0  = blockIdx.y * 128;

    unsigned long long acc[8][4];
#pragma unroll
    for (int i = 0; i < 8; i++)
#pragma unroll
        for (int j = 0; j < 4; j++) acc[i][j] = 0ull;

    const int lc = tid >> 1;               // 0..127 (row: c or gl)
    const int lm = (tid & 1) * 4;          // m sub-offset 0 or 4

    for (int m0 = 0; m0 < MOTIF; m0 += 8) {
        float4 wv4 = *(const float4*)&w[(c0 + lc) * MOTIF + m0 + lm];
        Wsd[lm + 0][lc] = make_float2(wv4.x, wv4.x);
        Wsd[lm + 1][lc] = make_float2(wv4.y, wv4.y);
        Wsd[lm + 2][lc] = make_float2(wv4.z, wv4.z);
        Wsd[lm + 3][lc] = make_float2(wv4.w, wv4.w);
        float4 xv4 = *(const float4*)&x[(size_t)(gl0 + lc) * MOTIF + m0 + lm];
        Xs[lm + 0][lc] = xv4.x;
        Xs[lm + 1][lc] = xv4.y;
        Xs[lm + 2][lc] = xv4.z;
        Xs[lm + 3][lc] = xv4.w;
        __syncthreads();

#pragma unroll
        for (int mm = 0; mm < 8; mm++) {
            const unsigned long long* xrow =
                reinterpret_cast<const unsigned long long*>(Xs[mm]);
            unsigned long long x2[4], w2[8];
#pragma unroll
            for (int j = 0; j < 4; j++) x2[j] = xrow[tx + j * 16];
#pragma unroll
            for (int i = 0; i < 8; i++)
                w2[i] = *reinterpret_cast<const unsigned long long*>(
                            &Wsd[mm][ty + i * 16]);
#pragma unroll
            for (int i = 0; i < 8; i++)
#pragma unroll
                for (int j = 0; j < 4; j++)
                    acc[i][j] = ffma2(w2[i], x2[j], acc[i][j]);
        }
        __syncthreads();
    }

#pragma unroll
    for (int i = 0; i < 8; i++) {
        const int c = c0 + ty + i * 16;
        const float bv = bias[c];
#pragma unroll
        for (int j = 0; j < 4; j++) {
            const int gl = gl0 + tx * 2 + j * 32;   // even; pair in same peak
            const int n  = gl / PSIZE;
            const int l  = gl - n * PSIZE;
            float2 a = u2f2(acc[i][j]);
            a.x += bv; a.y += bv;
            *(float2*)&g_buf[0][((size_t)n * HID + c) * MAXLEN + l] = a;
        }
    }
}

// ---------------------------------------------------------------------------
// Kernel 2: dilated conv layer (K=3) + bias + ReLU + residual (middle tap)
// Block: 128 co x 128 l per peak; CI chunks of 8; f32x2 packed math.
// Xs holds ONE union window of span = 128 + 2*dil floats per ci; the k-taps
// index into it at offset k*dil (dil even -> u64-index offset k*dil/2).
// ---------------------------------------------------------------------------
__global__ __launch_bounds__(256)
void conv_kernel(int src,
                 const float* __restrict__ w,     // [co][ci][3] this layer
                 const float* __restrict__ bias,  // [co]
                 int len_in, int len_out, int dil) {
    __shared__ float2 Wd[3][8][128];               // [k][ci][co] dup (w,w)
    __shared__ __align__(16) float Xs[8][384];     // [ci][union window]

    const float* __restrict__ in  = g_buf[src];
    float* __restrict__       out = g_buf[src ^ 1];

    const int tid = threadIdx.x;
    const int tx  = tid & 15;        // l-pair lane
    const int ty  = tid >> 4;        // co lane
    const int l0  = blockIdx.x * 128;
    const int co0 = blockIdx.y * 128;
    const int n   = blockIdx.z;
    const int span = 128 + 2 * dil;  // <= 384
    const int kd2  = dil >> 1;       // per-k offset in u64 units

    unsigned long long acc[8][4];
#pragma unroll
    for (int i = 0; i < 8; i++)
#pragma unroll
        for (int j = 0; j < 4; j++) acc[i][j] = 0ull;

    const int wco  = tid >> 1;
    const int woff = (tid & 1) * 12;

    for (int ci0 = 0; ci0 < HID; ci0 += 8) {
        // --- weights: 12 consecutive (ci,k) floats per thread, dup-scatter
        {
            const float* wp = &w[(size_t)(co0 + wco) * (HID * 3) + ci0 * 3 + woff];
            float4 a = *(const float4*)(wp + 0);
            float4 b = *(const float4*)(wp + 4);
            float4 c = *(const float4*)(wp + 8);
            float tmp[12] = {a.x, a.y, a.z, a.w, b.x, b.y, b.z, b.w,
                             c.x, c.y, c.z, c.w};
#pragma unroll
            for (int r = 0; r < 12; r++) {
                int q  = woff + r;
                int ci = q / 3;
                int k  = q - ci * 3;
                Wd[k][ci][wco] = make_float2(tmp[r], tmp[r]);
            }
        }
        // --- inputs: union window [l0, l0+span) per ci, zero-padded
#pragma unroll
        for (int ci = 0; ci < 8; ci++) {
            const float* rowp = &in[((size_t)n * HID + ci0 + ci) * MAXLEN];
            for (int l = tid; l < span; l += 256) {
                int g = l0 + l;
                Xs[ci][l] = (g < len_in) ? rowp[g] : 0.f;
            }
        }
        __syncthreads();

#pragma unroll
        for (int ci = 0; ci < 8; ci++) {
            const unsigned long long* xrow =
                reinterpret_cast<const unsigned long long*>(Xs[ci]);
#pragma unroll
            for (int k = 0; k < 3; k++) {
                unsigned long long x2[4], w2[8];
#pragma unroll
                for (int j = 0; j < 4; j++)
                    x2[j] = xrow[tx + j * 16 + k * kd2];
#pragma unroll
                for (int i = 0; i < 8; i++)
                    w2[i] = *reinterpret_cast<const unsigned long long*>(
                                &Wd[k][ci][ty + i * 16]);
#pragma unroll
                for (int i = 0; i < 8; i++)
#pragma unroll
                    for (int j = 0; j < 4; j++)
                        acc[i][j] = ffma2(w2[i], x2[j], acc[i][j]);
            }
        }
        __syncthreads();
    }

    // epilogue: bias + relu + residual (middle tap), float2 I/O (all even)
#pragma unroll
    for (int i = 0; i < 8; i++) {
        const int co = co0 + ty + i * 16;
        const float bv = bias[co];
        const float* resrow = &in[((size_t)n * HID + co) * MAXLEN];
        float* outrow = &out[((size_t)n * HID + co) * MAXLEN];
#pragma unroll
        for (int j = 0; j < 4; j++) {
            const int l = l0 + tx * 2 + j * 32;   // even; len_out even
            if (l < len_out) {
                float2 a = u2f2(acc[i][j]);
                float2 r = *(const float2*)&resrow[l + dil];  // dil even
                float2 v;
                v.x = fmaxf(a.x + bv, 0.f) + r.x;
                v.y = fmaxf(a.y + bv, 0.f) + r.y;
                *(float2*)&outrow[l] = v;
            }
        }
    }
}

// ---------------------------------------------------------------------------
// Kernel 3: per-(peak, channel) mean over length
// ---------------------------------------------------------------------------
__global__ __launch_bounds__(256)
void mean_kernel(int src, int len) {
    const float* __restrict__ in = g_buf[src];
    const int row  = blockIdx.x * 8 + (threadIdx.x >> 5);
    const int lane = threadIdx.x & 31;
    const float* p = in + (size_t)row * MAXLEN;
    float s = 0.f;
    for (int l = lane; l < len; l += 32) s += p[l];
#pragma unroll
    for (int o = 16; o; o >>= 1) s += __shfl_xor_sync(0xFFFFFFFFu, s, o);
    if (lane == 0) g_mean[row] = s / (float)len;
}

// ---------------------------------------------------------------------------
// Kernel 4: atpm head  out[n] = softplus(dot(mean[n], w_atpm) + b_atpm)
// ---------------------------------------------------------------------------
__global__ __launch_bounds__(256)
void atpm_kernel(const float* __restrict__ w, const float* __restrict__ b,
                 float* __restrict__ out) {
    __shared__ float sh[256];
    const int n = blockIdx.x;
    const int t = threadIdx.x;
    sh[t] = g_mean[n * HID + t] * w[t];
    __syncthreads();
    for (int s = 128; s > 0; s >>= 1) {
        if (t < s) sh[t] += sh[t + s];
        __syncthreads();
    }
    if (t == 0) out[n] = softplus_f(sh[0] + b[0]);
}

// ---------------------------------------------------------------------------
// Kernel 5: profile conv (K=75, 256 -> 1) + softplus
// ---------------------------------------------------------------------------
__global__ __launch_bounds__(256)
void prof_kernel(int src, const float* __restrict__ wp,
                 const float* __restrict__ bp, float* __restrict__ out,
                 int len_in, int len_out) {
    __shared__ float hrow[512];
    __shared__ float wrow[80];
    const float* __restrict__ in = g_buf[src];
    const int n = blockIdx.x;
    const int t = threadIdx.x;
    const int l0 = t;
    const int l1 = t + 256;

    float acc0 = 0.f, acc1 = 0.f;
    for (int c = 0; c < HID; c++) {
        for (int l = t; l < len_in; l += 256)
            hrow[l] = in[((size_t)n * HID + c) * MAXLEN + l];
        if (t < PROF_K) wrow[t] = wp[c * PROF_K + t];
        __syncthreads();

#pragma unroll 5
        for (int k = 0; k < PROF_K; k++)
            acc0 = fmaf(hrow[l0 + k], wrow[k], acc0);
        if (l1 < len_out) {
#pragma unroll 5
            for (int k = 0; k < PROF_K; k++)
                acc1 = fmaf(hrow[l1 + k], wrow[k], acc1);
        }
        __syncthreads();
    }
    const float bv = bp[0];
    out[PEAKS + (size_t)n * len_out + l0] = softplus_f(acc0 + bv);
    if (l1 < len_out)
        out[PEAKS + (size_t)n * len_out + l1] = softplus_f(acc1 + bv);
}

// ---------------------------------------------------------------------------
// Launch
// ---------------------------------------------------------------------------
extern "C" void kernel_launch(void* const* d_in, const int* in_sizes, int n_in,
                              void* d_out, int out_size) {
    const float* x = (const float*)d_in[0];

    int iw = -1;
    for (int i = 1; i < n_in; i++)
        if (in_sizes[i] == MOTIF * HID) { iw = i; break; }

    const float* w_proj = (const float*)d_in[iw + 0];
    const float* b_proj = (const float*)d_in[iw + 1];
    const float* w_dil  = (const float*)d_in[iw + 2];
    const float* b_dil  = (const float*)d_in[iw + 3];
    const float* w_prof = (const float*)d_in[iw + 4];
    const float* b_prof = (const float*)d_in[iw + 5];
    const float* w_atpm = (const float*)d_in[iw + 6];
    const float* b_atpm = (const float*)d_in[iw + 7];
    float* out = (float*)d_out;

    // 1) projection -> g_buf[0]
    proj_kernel<<<dim3(GL_TOTAL / 128, HID / 128), 256>>>(x, w_proj, b_proj);

    // 2) dilated conv tower (ping-pong)
    int len = PSIZE, src = 0;
    for (int i = 0; i < DEPTH; i++) {
        const int d  = 1 << (i + 1);
        const int lo = len - 2 * d;
        conv_kernel<<<dim3((lo + 127) / 128, HID / 128, PEAKS), 256>>>(
            src, w_dil + (size_t)i * HID * HID * 3, b_dil + i * HID, len, lo, d);
        src ^= 1;
        len = lo;
    }

    // 3) mean over length (final map: len == 492)
    mean_kernel<<<(PEAKS * HID) / 8, 256>>>(src, len);

    // 4) atpm head -> out[0..127]
    atpm_kernel<<<PEAKS, 256>>>(w_atpm, b_atpm, out);

    // 5) profile conv -> out[128 .. 128 + 128*418)
    prof_kernel<<<PEAKS, 256>>>(src, w_prof, b_prof, out, len, len - PROF_K + 1);
}

// round 6
// speedup vs baseline: 1.4200x; 1.4200x over previous
#include <cuda_runtime.h>
#include <math.h>
#include <stdint.h>

// ---------------------------------------------------------------------------
// Fixed problem shapes (fast path: uniform peaks)
// ---------------------------------------------------------------------------
#define BATCH      2
#define NUM_PEAKS  64
#define PEAKS      128          // BATCH * NUM_PEAKS
#define PSIZE      1000
#define MOTIF      640
#define HID        256
#define DEPTH      7
#define PROF_K     75
#define MAXLEN     1008         // padded row stride (floats)
#define GL_TOTAL   128000       // BATCH * NUM_PEAKS * PSIZE

// conv dynamic smem partition (bytes)
#define WD_BYTES   49536        // [2][3][8][129] float2
#define XS_BYTES   24576        // [2][8][384] float
#define WST_BYTES  24576        // [2][3072] float
#define CONV_SMEM  (WD_BYTES + XS_BYTES + WST_BYTES)   // 98688

// Ping-pong activation buffers: [2][peak][channel][MAXLEN]
__device__ float g_buf[2][PEAKS * HID * MAXLEN];
// Per-(peak, channel) mean of the final feature map
__device__ float g_mean[PEAKS * HID];

__device__ __forceinline__ float softplus_f(float x) {
    return (x > 20.f) ? x : log1pf(expf(x));
}

// Packed dual-fp32 FMA (sm_100+): d = a*b + c on both 32-bit halves
__device__ __forceinline__ unsigned long long ffma2(unsigned long long a,
                                                    unsigned long long b,
                                                    unsigned long long c) {
    unsigned long long d;
    asm("fma.rn.f32x2 %0, %1, %2, %3;" : "=l"(d) : "l"(a), "l"(b), "l"(c));
    return d;
}

__device__ __forceinline__ float2 u2f2(unsigned long long u) {
    float2 f;
    asm("mov.b64 {%0, %1}, %2;" : "=f"(f.x), "=f"(f.y) : "l"(u));
    return f;
}

// cp.async helpers
__device__ __forceinline__ void cpa8(uint32_t dst, const void* src, int sz) {
    asm volatile("cp.async.ca.shared.global [%0], [%1], 8, %2;"
                 :: "r"(dst), "l"(src), "r"(sz));
}
__device__ __forceinline__ void cpa16(uint32_t dst, const void* src) {
    asm volatile("cp.async.ca.shared.global [%0], [%1], 16;"
                 :: "r"(dst), "l"(src));
}
__device__ __forceinline__ void cpa_commit() {
    asm volatile("cp.async.commit_group;");
}
__device__ __forceinline__ void cpa_wait0() {
    asm volatile("cp.async.wait_group 0;");
}

// ---------------------------------------------------------------------------
// Kernel 1: 1x1 motif projection  h[n][c][l] = sum_m x[gl][m] * w[c][m] + b[c]
// 128 gl x 128 c per block, 256 threads, f32x2 packed math (unchanged R4).
// ---------------------------------------------------------------------------
__global__ __launch_bounds__(256)
void proj_kernel(const float* __restrict__ x,
                 const float* __restrict__ w,
                 const float* __restrict__ bias) {
    __shared__ float2 Wsd[8][128];                 // [m][c] duplicated (w,w)
    __shared__ __align__(16) float Xs[8][128];     // [m][gl]

    const int tid = threadIdx.x;
    const int tx  = tid & 15;       // gl-pair lane
    const int ty  = tid >> 4;       // c lane
    const int gl0 = blockIdx.x * 128;
    const int c0  = blockIdx.y * 128;

    unsigned long long acc[8][4];
#pragma unroll
    for (int i = 0; i < 8; i++)
#pragma unroll
        for (int j = 0; j < 4; j++) acc[i][j] = 0ull;

    const int lc = tid >> 1;
    const int lm = (tid & 1) * 4;

    for (int m0 = 0; m0 < MOTIF; m0 += 8) {
        float4 wv4 = *(const float4*)&w[(c0 + lc) * MOTIF + m0 + lm];
        Wsd[lm + 0][lc] = make_float2(wv4.x, wv4.x);
        Wsd[lm + 1][lc] = make_float2(wv4.y, wv4.y);
        Wsd[lm + 2][lc] = make_float2(wv4.z, wv4.z);
        Wsd[lm + 3][lc] = make_float2(wv4.w, wv4.w);
        float4 xv4 = *(const float4*)&x[(size_t)(gl0 + lc) * MOTIF + m0 + lm];
        Xs[lm + 0][lc] = xv4.x;
        Xs[lm + 1][lc] = xv4.y;
        Xs[lm + 2][lc] = xv4.z;
        Xs[lm + 3][lc] = xv4.w;
        __syncthreads();

#pragma unroll
        for (int mm = 0; mm < 8; mm++) {
            const unsigned long long* xrow =
                reinterpret_cast<const unsigned long long*>(Xs[mm]);
            unsigned long long x2v[4], w2v[8];
#pragma unroll
            for (int j = 0; j < 4; j++) x2v[j] = xrow[tx + j * 16];
#pragma unroll
            for (int i = 0; i < 8; i++)
                w2v[i] = *reinterpret_cast<const unsigned long long*>(
                             &Wsd[mm][ty + i * 16]);
#pragma unroll
            for (int i = 0; i < 8; i++)
#pragma unroll
                for (int j = 0; j < 4; j++)
                    acc[i][j] = ffma2(w2v[i], x2v[j], acc[i][j]);
        }
        __syncthreads();
    }

#pragma unroll
    for (int i = 0; i < 8; i++) {
        const int c = c0 + ty + i * 16;
        const float bv = bias[c];
#pragma unroll
        for (int j = 0; j < 4; j++) {
            const int gl = gl0 + tx * 2 + j * 32;
            const int n  = gl / PSIZE;
            const int l  = gl - n * PSIZE;
            float2 a = u2f2(acc[i][j]);
            a.x += bv; a.y += bv;
            *(float2*)&g_buf[0][((size_t)n * HID + c) * MAXLEN + l] = a;
        }
    }
}

// ---------------------------------------------------------------------------
// Kernel 2: dilated conv (K=3) + bias + ReLU + residual, f32x2 math,
// DOUBLE-BUFFERED pipeline: cp.async prefetch of Xs (zfill pad) and weight
// staging (Wst) for chunk c+1 overlapped with math on chunk c.
// Block: 128 co x 128 l per peak; CI chunks of 8.
// ---------------------------------------------------------------------------
__global__ __launch_bounds__(256, 2)
void conv_kernel(int src,
                 const float* __restrict__ w,     // [co][ci][3] this layer
                 const float* __restrict__ bias,  // [co]
                 int len_in, int len_out, int dil) {
    extern __shared__ __align__(16) char smraw[];
    // Wd[buf][k][ci][co]  (co dim padded to 129 -> STS bank-conflict free)
    float2 (*Wd)[3][8][129] = (float2(*)[3][8][129])smraw;
    float  (*Xs)[8][384]    = (float(*)[8][384])(smraw + WD_BYTES);
    float  (*Wst)[3072]     = (float(*)[3072])(smraw + WD_BYTES + XS_BYTES);

    const float* __restrict__ in  = g_buf[src];
    float* __restrict__       out = g_buf[src ^ 1];

    const int tid = threadIdx.x;
    const int tx  = tid & 15;        // l-pair lane
    const int ty  = tid >> 4;        // co lane
    const int l0  = blockIdx.x * 128;
    const int co0 = blockIdx.y * 128;
    const int n   = blockIdx.z;
    const int kd2   = dil >> 1;            // per-k tap offset in u64 units
    const int span2 = 64 + dil;            // u64 elems per Xs row (<=192)
    const int total64 = 8 * span2;

    const int wco  = tid >> 1;
    const int woff = (tid & 1) * 12;

    const uint32_t xs_sa  = (uint32_t)__cvta_generic_to_shared(&Xs[0][0][0]);
    const uint32_t wst_sa = (uint32_t)__cvta_generic_to_shared(&Wst[0][0]);
    const float* rowbase  = &in[(size_t)n * HID * MAXLEN];
    const float* wbase    = &w[(size_t)(co0 + wco) * (HID * 3) + woff];

    unsigned long long acc[8][4];
#pragma unroll
    for (int i = 0; i < 8; i++)
#pragma unroll
        for (int j = 0; j < 4; j++) acc[i][j] = 0ull;

    // ---- pipeline stage helpers -------------------------------------------
    auto issue_loads = [&](int chunk, int b) {
        const int ci0 = chunk * 8;
        // weights: 12 consecutive floats per thread -> linear staging
        const float* wp = wbase + ci0 * 3;
        const uint32_t wdst = wst_sa + (uint32_t)(b * 3072 + tid * 12) * 4u;
        cpa16(wdst,      wp);
        cpa16(wdst + 16, wp + 4);
        cpa16(wdst + 32, wp + 8);
        // inputs: 8 rows x span2 u64, zero-fill past len_in
        const float* rb = rowbase + (size_t)ci0 * MAXLEN;
        const uint32_t xb = xs_sa + (uint32_t)b * (8 * 384 * 4);
        for (int e = tid; e < total64; e += 256) {
            const int ci = e / span2;
            const int p  = e - ci * span2;
            const int g  = l0 + 2 * p;
            cpa8(xb + (uint32_t)(ci * 384 + 2 * p) * 4u,
                 rb + (size_t)ci * MAXLEN + g,
                 (g < len_in) ? 8 : 0);
        }
        cpa_commit();
    };

    auto scatter_w = [&](int b) {
        const float* ws = &Wst[b][tid * 12];
        float4 a4 = *(const float4*)(ws + 0);
        float4 b4 = *(const float4*)(ws + 4);
        float4 c4 = *(const float4*)(ws + 8);
        float tmp[12] = {a4.x, a4.y, a4.z, a4.w, b4.x, b4.y, b4.z, b4.w,
                         c4.x, c4.y, c4.z, c4.w};
#pragma unroll
        for (int r = 0; r < 12; r++) {
            const int q  = woff + r;
            const int ci = q / 3;
            const int k  = q - ci * 3;
            Wd[b][k][ci][wco] = make_float2(tmp[r], tmp[r]);
        }
    };

    // ---- prologue: chunk 0 -------------------------------------------------
    issue_loads(0, 0);
    cpa_wait0();
    scatter_w(0);
    __syncthreads();

    // ---- main pipelined loop over 32 ci-chunks -----------------------------
    for (int c = 0; c < 32; c++) {
        const int cur = c & 1;
        const int nb  = cur ^ 1;
        if (c < 31) issue_loads(c + 1, nb);

        // math on current chunk
#pragma unroll
        for (int ci = 0; ci < 8; ci++) {
            const unsigned long long* xrow =
                reinterpret_cast<const unsigned long long*>(Xs[cur][ci]);
#pragma unroll
            for (int k = 0; k < 3; k++) {
                unsigned long long x2v[4], w2v[8];
#pragma unroll
                for (int j = 0; j < 4; j++)
                    x2v[j] = xrow[tx + j * 16 + k * kd2];
#pragma unroll
                for (int i = 0; i < 8; i++)
                    w2v[i] = *reinterpret_cast<const unsigned long long*>(
                                 &Wd[cur][k][ci][ty + i * 16]);
#pragma unroll
                for (int i = 0; i < 8; i++)
#pragma unroll
                    for (int j = 0; j < 4; j++)
                        acc[i][j] = ffma2(w2v[i], x2v[j], acc[i][j]);
            }
        }

        if (c < 31) {
            cpa_wait0();       // Xs[nb] + Wst[nb] arrived (overlapped w/ math)
            scatter_w(nb);     // Wst[nb] -> Wd[nb] dup-scatter
        }
        __syncthreads();
    }

    // ---- epilogue: bias + relu + residual (middle tap), float2 I/O ---------
#pragma unroll
    for (int i = 0; i < 8; i++) {
        const int co = co0 + ty + i * 16;
        const float bv = bias[co];
        const float* resrow = &in[((size_t)n * HID + co) * MAXLEN];
        float* outrow = &out[((size_t)n * HID + co) * MAXLEN];
#pragma unroll
        for (int j = 0; j < 4; j++) {
            const int l = l0 + tx * 2 + j * 32;   // even; len_out even
            if (l < len_out) {
                float2 a = u2f2(acc[i][j]);
                float2 r = *(const float2*)&resrow[l + dil];  // dil even
                float2 v;
                v.x = fmaxf(a.x + bv, 0.f) + r.x;
                v.y = fmaxf(a.y + bv, 0.f) + r.y;
                *(float2*)&outrow[l] = v;
            }
        }
    }
}

// ---------------------------------------------------------------------------
// Kernel 3: per-(peak, channel) mean over length
// ---------------------------------------------------------------------------
__global__ __launch_bounds__(256)
void mean_kernel(int src, int len) {
    const float* __restrict__ in = g_buf[src];
    const int row  = blockIdx.x * 8 + (threadIdx.x >> 5);
    const int lane = threadIdx.x & 31;
    const float* p = in + (size_t)row * MAXLEN;
    float s = 0.f;
    for (int l = lane; l < len; l += 32) s += p[l];
#pragma unroll
    for (int o = 16; o; o >>= 1) s += __shfl_xor_sync(0xFFFFFFFFu, s, o);
    if (lane == 0) g_mean[row] = s / (float)len;
}

// ---------------------------------------------------------------------------
// Kernel 4: atpm head  out[n] = softplus(dot(mean[n], w_atpm) + b_atpm)
// ---------------------------------------------------------------------------
__global__ __launch_bounds__(256)
void atpm_kernel(const float* __restrict__ w, const float* __restrict__ b,
                 float* __restrict__ out) {
    __shared__ float sh[256];
    const int n = blockIdx.x;
    const int t = threadIdx.x;
    sh[t] = g_mean[n * HID + t] * w[t];
    __syncthreads();
    for (int s = 128; s > 0; s >>= 1) {
        if (t < s) sh[t] += sh[t + s];
        __syncthreads();
    }
    if (t == 0) out[n] = softplus_f(sh[0] + b[0]);
}

// ---------------------------------------------------------------------------
// Kernel 5: profile conv (K=75, 256 -> 1) + softplus
// ---------------------------------------------------------------------------
__global__ __launch_bounds__(256)
void prof_kernel(int src, const float* __restrict__ wp,
                 const float* __restrict__ bp, float* __restrict__ out,
                 int len_in, int len_out) {
    __shared__ float hrow[512];
    __shared__ float wrow[80];
    const float* __restrict__ in = g_buf[src];
    const int n = blockIdx.x;
    const int t = threadIdx.x;
    const int l0 = t;
    const int l1 = t + 256;

    float acc0 = 0.f, acc1 = 0.f;
    for (int c = 0; c < HID; c++) {
        for (int l = t; l < len_in; l += 256)
            hrow[l] = in[((size_t)n * HID + c) * MAXLEN + l];
        if (t < PROF_K) wrow[t] = wp[c * PROF_K + t];
        __syncthreads();

#pragma unroll 5
        for (int k = 0; k < PROF_K; k++)
            acc0 = fmaf(hrow[l0 + k], wrow[k], acc0);
        if (l1 < len_out) {
#pragma unroll 5
            for (int k = 0; k < PROF_K; k++)
                acc1 = fmaf(hrow[l1 + k], wrow[k], acc1);
        }
        __syncthreads();
    }
    const float bv = bp[0];
    out[PEAKS + (size_t)n * len_out + l0] = softplus_f(acc0 + bv);
    if (l1 < len_out)
        out[PEAKS + (size_t)n * len_out + l1] = softplus_f(acc1 + bv);
}

// ---------------------------------------------------------------------------
// Launch
// ---------------------------------------------------------------------------
extern "C" void kernel_launch(void* const* d_in, const int* in_sizes, int n_in,
                              void* d_out, int out_size) {
    const float* x = (const float*)d_in[0];

    int iw = -1;
    for (int i = 1; i < n_in; i++)
        if (in_sizes[i] == MOTIF * HID) { iw = i; break; }

    const float* w_proj = (const float*)d_in[iw + 0];
    const float* b_proj = (const float*)d_in[iw + 1];
    const float* w_dil  = (const float*)d_in[iw + 2];
    const float* b_dil  = (const float*)d_in[iw + 3];
    const float* w_prof = (const float*)d_in[iw + 4];
    const float* b_prof = (const float*)d_in[iw + 5];
    const float* w_atpm = (const float*)d_in[iw + 6];
    const float* b_atpm = (const float*)d_in[iw + 7];
    float* out = (float*)d_out;

    cudaFuncSetAttribute(conv_kernel,
                         cudaFuncAttributeMaxDynamicSharedMemorySize,
                         CONV_SMEM);

    // 1) projection -> g_buf[0]
    proj_kernel<<<dim3(GL_TOTAL / 128, HID / 128), 256>>>(x, w_proj, b_proj);

    // 2) dilated conv tower (ping-pong)
    int len = PSIZE, src = 0;
    for (int i = 0; i < DEPTH; i++) {
        const int d  = 1 << (i + 1);
        const int lo = len - 2 * d;
        conv_kernel<<<dim3((lo + 127) / 128, HID / 128, PEAKS), 256,
                      CONV_SMEM>>>(
            src, w_dil + (size_t)i * HID * HID * 3, b_dil + i * HID, len, lo, d);
        src ^= 1;
        len = lo;
    }

    // 3) mean over length (final map: len == 492)
    mean_kernel<<<(PEAKS * HID) / 8, 256>>>(src, len);

    // 4) atpm head -> out[0..127]
    atpm_kernel<<<PEAKS, 256>>>(w_atpm, b_atpm, out);

    // 5) profile conv -> out[128 .. 128 + 128*418)
    prof_kernel<<<PEAKS, 256>>>(src, w_prof, b_prof, out, len, len - PROF_K + 1);
}

// round 7
// speedup vs baseline: 1.6476x; 1.1603x over previous
#include <cuda_runtime.h>
#include <math.h>
#include <stdint.h>

// ---------------------------------------------------------------------------
// Fixed problem shapes (fast path: uniform peaks)
// ---------------------------------------------------------------------------
#define BATCH      2
#define NUM_PEAKS  64
#define PEAKS      128          // BATCH * NUM_PEAKS
#define PSIZE      1000
#define MOTIF      640
#define HID        256
#define DEPTH      7
#define PROF_K     75
#define MAXLEN     1008         // padded row stride (floats)
#define GL_TOTAL   128000       // BATCH * NUM_PEAKS * PSIZE

// conv dynamic smem partition (bytes)
#define WSM_STRIDE 28                       // floats per co row (24 used)
#define WSM_BYTES  (2 * 128 * WSM_STRIDE * 4)   // 28672
#define XS_BYTES   (2 * 8 * 384 * 4)            // 24576
#define CONV_SMEM  (WSM_BYTES + XS_BYTES)       // 53248

// Ping-pong activation buffers: [2][peak][channel][MAXLEN]
__device__ float g_buf[2][PEAKS * HID * MAXLEN];
// Per-(peak, channel) mean of the final feature map
__device__ float g_mean[PEAKS * HID];

__device__ __forceinline__ float softplus_f(float x) {
    return (x > 20.f) ? x : log1pf(expf(x));
}

// Packed dual-fp32 FMA (sm_100+): d = a*b + c on both 32-bit halves
__device__ __forceinline__ unsigned long long ffma2(unsigned long long a,
                                                    unsigned long long b,
                                                    unsigned long long c) {
    unsigned long long d;
    asm("fma.rn.f32x2 %0, %1, %2, %3;" : "=l"(d) : "l"(a), "l"(b), "l"(c));
    return d;
}

// duplicate one fp32 into both halves of a 64-bit pair
__device__ __forceinline__ unsigned long long dupf(float w) {
    unsigned long long d;
    asm("mov.b64 %0, {%1, %1};" : "=l"(d) : "f"(w));
    return d;
}

__device__ __forceinline__ float2 u2f2(unsigned long long u) {
    float2 f;
    asm("mov.b64 {%0, %1}, %2;" : "=f"(f.x), "=f"(f.y) : "l"(u));
    return f;
}

// cp.async helpers
__device__ __forceinline__ void cpa8(uint32_t dst, const void* src, int sz) {
    asm volatile("cp.async.ca.shared.global [%0], [%1], 8, %2;"
                 :: "r"(dst), "l"(src), "r"(sz));
}
__device__ __forceinline__ void cpa16(uint32_t dst, const void* src) {
    asm volatile("cp.async.ca.shared.global [%0], [%1], 16;"
                 :: "r"(dst), "l"(src));
}
__device__ __forceinline__ void cpa_commit() {
    asm volatile("cp.async.commit_group;");
}
__device__ __forceinline__ void cpa_wait0() {
    asm volatile("cp.async.wait_group 0;");
}

// ---------------------------------------------------------------------------
// Kernel 1: 1x1 motif projection  h[n][c][l] = sum_m x[gl][m] * w[c][m] + b[c]
// 128 gl x 128 c per block, 256 threads; scalar weights + register dup.
// ---------------------------------------------------------------------------
__global__ __launch_bounds__(256)
void proj_kernel(const float* __restrict__ x,
                 const float* __restrict__ w,
                 const float* __restrict__ bias) {
    __shared__ float Ws[8][128];                   // [m][c] scalar
    __shared__ __align__(16) float Xs[8][128];     // [m][gl]

    const int tid = threadIdx.x;
    const int tx  = tid & 15;       // gl-pair lane
    const int ty  = tid >> 4;       // c lane
    const int gl0 = blockIdx.x * 128;
    const int c0  = blockIdx.y * 128;

    unsigned long long acc[8][4];
#pragma unroll
    for (int i = 0; i < 8; i++)
#pragma unroll
        for (int j = 0; j < 4; j++) acc[i][j] = 0ull;

    const int lc = tid >> 1;
    const int lm = (tid & 1) * 4;

    for (int m0 = 0; m0 < MOTIF; m0 += 8) {
        float4 wv4 = *(const float4*)&w[(c0 + lc) * MOTIF + m0 + lm];
        Ws[lm + 0][lc] = wv4.x;
        Ws[lm + 1][lc] = wv4.y;
        Ws[lm + 2][lc] = wv4.z;
        Ws[lm + 3][lc] = wv4.w;
        float4 xv4 = *(const float4*)&x[(size_t)(gl0 + lc) * MOTIF + m0 + lm];
        Xs[lm + 0][lc] = xv4.x;
        Xs[lm + 1][lc] = xv4.y;
        Xs[lm + 2][lc] = xv4.z;
        Xs[lm + 3][lc] = xv4.w;
        __syncthreads();

#pragma unroll
        for (int mm = 0; mm < 8; mm++) {
            const unsigned long long* xrow =
                reinterpret_cast<const unsigned long long*>(Xs[mm]);
            unsigned long long x2v[4];
#pragma unroll
            for (int j = 0; j < 4; j++) x2v[j] = xrow[tx + j * 16];
#pragma unroll
            for (int i = 0; i < 8; i++) {
                const unsigned long long wd = dupf(Ws[mm][ty + i * 16]);
#pragma unroll
                for (int j = 0; j < 4; j++)
                    acc[i][j] = ffma2(wd, x2v[j], acc[i][j]);
            }
        }
        __syncthreads();
    }

#pragma unroll
    for (int i = 0; i < 8; i++) {
        const int c = c0 + ty + i * 16;
        const float bv = bias[c];
#pragma unroll
        for (int j = 0; j < 4; j++) {
            const int gl = gl0 + tx * 2 + j * 32;
            const int n  = gl / PSIZE;
            const int l  = gl - n * PSIZE;
            float2 a = u2f2(acc[i][j]);
            a.x += bv; a.y += bv;
            *(float2*)&g_buf[0][((size_t)n * HID + c) * MAXLEN + l] = a;
        }
    }
}

// ---------------------------------------------------------------------------
// Kernel 2: dilated conv (K=3) + bias + ReLU + residual, f32x2 math,
// double-buffered cp.async pipeline. Weights staged DIRECTLY via cp.async
// into Wsm[buf][co][28] (24 taps of this chunk per co row, no scatter);
// math loads weights as scalar LDS.32 (warp broadcast) + register dup.
// Block: 128 co x 128 l per peak; CI chunks of 8.
// ---------------------------------------------------------------------------
__global__ __launch_bounds__(256, 2)
void conv_kernel(int src,
                 const float* __restrict__ w,     // [co][ci][3] this layer
                 const float* __restrict__ bias,  // [co]
                 int len_in, int len_out, int dil) {
    extern __shared__ __align__(16) char smraw[];
    float (*Wsm)[128][WSM_STRIDE] = (float(*)[128][WSM_STRIDE])smraw;
    float (*Xs)[8][384]           = (float(*)[8][384])(smraw + WSM_BYTES);

    const float* __restrict__ in  = g_buf[src];
    float* __restrict__       out = g_buf[src ^ 1];

    const int tid = threadIdx.x;
    const int tx  = tid & 15;        // l-pair lane
    const int ty  = tid >> 4;        // co lane
    const int l0  = blockIdx.x * 128;
    const int co0 = blockIdx.y * 128;
    const int n   = blockIdx.z;
    const int kd2   = dil >> 1;            // per-k tap offset in u64 units
    const int span2 = 64 + dil;            // u64 elems per Xs row (<=192)
    const int total64 = 8 * span2;

    const int wco  = tid >> 1;             // 0..127
    const int woff = (tid & 1) * 12;       // 0 or 12

    const uint32_t xs_sa  = (uint32_t)__cvta_generic_to_shared(&Xs[0][0][0]);
    const uint32_t wsm_sa = (uint32_t)__cvta_generic_to_shared(&Wsm[0][0][0]);
    const float* rowbase  = &in[(size_t)n * HID * MAXLEN];
    const float* wbase    = &w[(size_t)(co0 + wco) * (HID * 3) + woff];

    unsigned long long acc[8][4];
#pragma unroll
    for (int i = 0; i < 8; i++)
#pragma unroll
        for (int j = 0; j < 4; j++) acc[i][j] = 0ull;

    // ---- pipeline stage: issue cp.async for chunk -> buffer b --------------
    auto issue_loads = [&](int chunk, int b) {
        // weights: this thread's 12 consecutive floats of row co=wco,
        // landing at Wsm[b][wco][woff .. woff+12)
        const float* wp = wbase + chunk * 24;
        const uint32_t wdst =
            wsm_sa + (uint32_t)((b * 128 + wco) * WSM_STRIDE + woff) * 4u;
        cpa16(wdst,      wp);
        cpa16(wdst + 16, wp + 4);
        cpa16(wdst + 32, wp + 8);
        // inputs: 8 rows x span2 u64, zero-fill past len_in
        const float* rb = rowbase + (size_t)(chunk * 8) * MAXLEN;
        const uint32_t xb = xs_sa + (uint32_t)b * (8 * 384 * 4);
        for (int e = tid; e < total64; e += 256) {
            const int ci = e / span2;
            const int p  = e - ci * span2;
            const int g  = l0 + 2 * p;
            cpa8(xb + (uint32_t)(ci * 384 + 2 * p) * 4u,
                 rb + (size_t)ci * MAXLEN + g,
                 (g < len_in) ? 8 : 0);
        }
        cpa_commit();
    };

    // ---- prologue: chunk 0 -------------------------------------------------
    issue_loads(0, 0);
    cpa_wait0();
    __syncthreads();

    // ---- main pipelined loop over 32 ci-chunks -----------------------------
    for (int c = 0; c < 32; c++) {
        const int cur = c & 1;
        if (c < 31) issue_loads(c + 1, cur ^ 1);

        // math on current chunk
#pragma unroll
        for (int ci = 0; ci < 8; ci++) {
            const unsigned long long* xrow =
                reinterpret_cast<const unsigned long long*>(Xs[cur][ci]);
#pragma unroll
            for (int k = 0; k < 3; k++) {
                unsigned long long x2v[4];
#pragma unroll
                for (int j = 0; j < 4; j++)
                    x2v[j] = xrow[tx + j * 16 + k * kd2];
#pragma unroll
                for (int i = 0; i < 8; i++) {
                    const unsigned long long wd =
                        dupf(Wsm[cur][ty + i * 16][ci * 3 + k]);
#pragma unroll
                    for (int j = 0; j < 4; j++)
                        acc[i][j] = ffma2(wd, x2v[j], acc[i][j]);
                }
            }
        }

        if (c < 31) cpa_wait0();   // next chunk arrived (overlapped w/ math)
        __syncthreads();
    }

    // ---- epilogue: bias + relu + residual (middle tap), float2 I/O ---------
#pragma unroll
    for (int i = 0; i < 8; i++) {
        const int co = co0 + ty + i * 16;
        const float bv = bias[co];
        const float* resrow = &in[((size_t)n * HID + co) * MAXLEN];
        float* outrow = &out[((size_t)n * HID + co) * MAXLEN];
#pragma unroll
        for (int j = 0; j < 4; j++) {
            const int l = l0 + tx * 2 + j * 32;   // even; len_out even
            if (l < len_out) {
                float2 a = u2f2(acc[i][j]);
                float2 r = *(const float2*)&resrow[l + dil];  // dil even
                float2 v;
                v.x = fmaxf(a.x + bv, 0.f) + r.x;
                v.y = fmaxf(a.y + bv, 0.f) + r.y;
                *(float2*)&outrow[l] = v;
            }
        }
    }
}

// ---------------------------------------------------------------------------
// Kernel 3: per-(peak, channel) mean over length
// ---------------------------------------------------------------------------
__global__ __launch_bounds__(256)
void mean_kernel(int src, int len) {
    const float* __restrict__ in = g_buf[src];
    const int row  = blockIdx.x * 8 + (threadIdx.x >> 5);
    const int lane = threadIdx.x & 31;
    const float* p = in + (size_t)row * MAXLEN;
    float s = 0.f;
    for (int l = lane; l < len; l += 32) s += p[l];
#pragma unroll
    for (int o = 16; o; o >>= 1) s += __shfl_xor_sync(0xFFFFFFFFu, s, o);
    if (lane == 0) g_mean[row] = s / (float)len;
}

// ---------------------------------------------------------------------------
// Kernel 4: atpm head  out[n] = softplus(dot(mean[n], w_atpm) + b_atpm)
// ---------------------------------------------------------------------------
__global__ __launch_bounds__(256)
void atpm_kernel(const float* __restrict__ w, const float* __restrict__ b,
                 float* __restrict__ out) {
    __shared__ float sh[256];
    const int n = blockIdx.x;
    const int t = threadIdx.x;
    sh[t] = g_mean[n * HID + t] * w[t];
    __syncthreads();
    for (int s = 128; s > 0; s >>= 1) {
        if (t < s) sh[t] += sh[t + s];
        __syncthreads();
    }
    if (t == 0) out[n] = softplus_f(sh[0] + b[0]);
}

// ---------------------------------------------------------------------------
// Kernel 5: profile conv (K=75, 256 -> 1) + softplus
// ---------------------------------------------------------------------------
__global__ __launch_bounds__(256)
void prof_kernel(int src, const float* __restrict__ wp,
                 const float* __restrict__ bp, float* __restrict__ out,
                 int len_in, int len_out) {
    __shared__ float hrow[512];
    __shared__ float wrow[80];
    const float* __restrict__ in = g_buf[src];
    const int n = blockIdx.x;
    const int t = threadIdx.x;
    const int l0 = t;
    const int l1 = t + 256;

    float acc0 = 0.f, acc1 = 0.f;
    for (int c = 0; c < HID; c++) {
        for (int l = t; l < len_in; l += 256)
            hrow[l] = in[((size_t)n * HID + c) * MAXLEN + l];
        if (t < PROF_K) wrow[t] = wp[c * PROF_K + t];
        __syncthreads();

#pragma unroll 5
        for (int k = 0; k < PROF_K; k++)
            acc0 = fmaf(hrow[l0 + k], wrow[k], acc0);
        if (l1 < len_out) {
#pragma unroll 5
            for (int k = 0; k < PROF_K; k++)
                acc1 = fmaf(hrow[l1 + k], wrow[k], acc1);
        }
        __syncthreads();
    }
    const float bv = bp[0];
    out[PEAKS + (size_t)n * len_out + l0] = softplus_f(acc0 + bv);
    if (l1 < len_out)
        out[PEAKS + (size_t)n * len_out + l1] = softplus_f(acc1 + bv);
}

// ---------------------------------------------------------------------------
// Launch
// ---------------------------------------------------------------------------
extern "C" void kernel_launch(void* const* d_in, const int* in_sizes, int n_in,
                              void* d_out, int out_size) {
    const float* x = (const float*)d_in[0];

    int iw = -1;
    for (int i = 1; i < n_in; i++)
        if (in_sizes[i] == MOTIF * HID) { iw = i; break; }

    const float* w_proj = (const float*)d_in[iw + 0];
    const float* b_proj = (const float*)d_in[iw + 1];
    const float* w_dil  = (const float*)d_in[iw + 2];
    const float* b_dil  = (const float*)d_in[iw + 3];
    const float* w_prof = (const float*)d_in[iw + 4];
    const float* b_prof = (const float*)d_in[iw + 5];
    const float* w_atpm = (const float*)d_in[iw + 6];
    const float* b_atpm = (const float*)d_in[iw + 7];
    float* out = (float*)d_out;

    cudaFuncSetAttribute(conv_kernel,
                         cudaFuncAttributeMaxDynamicSharedMemorySize,
                         CONV_SMEM);

    // 1) projection -> g_buf[0]
    proj_kernel<<<dim3(GL_TOTAL / 128, HID / 128), 256>>>(x, w_proj, b_proj);

    // 2) dilated conv tower (ping-pong)
    int len = PSIZE, src = 0;
    for (int i = 0; i < DEPTH; i++) {
        const int d  = 1 << (i + 1);
        const int lo = len - 2 * d;
        conv_kernel<<<dim3((lo + 127) / 128, HID / 128, PEAKS), 256,
                      CONV_SMEM>>>(
            src, w_dil + (size_t)i * HID * HID * 3, b_dil + i * HID, len, lo, d);
        src ^= 1;
        len = lo;
    }

    // 3) mean over length (final map: len == 492)
    mean_kernel<<<(PEAKS * HID) / 8, 256>>>(src, len);

    // 4) atpm head -> out[0..127]
    atpm_kernel<<<PEAKS, 256>>>(w_atpm, b_atpm, out);

    // 5) profile conv -> out[128 .. 128 + 128*418)
    prof_kernel<<<PEAKS, 256>>>(src, w_prof, b_prof, out, len, len - PROF_K + 1);
}